// round 10
// baseline (speedup 1.0000x reference)
#include <cuda_runtime.h>
#include <math_constants.h>

#define B_      8
#define H_      32
#define DK_     128
#define DM_     4096
#define MAXLEN_ 4096
#define SPLIT_  4
#define KSPLIT_ 4

// Scratch (no allocation allowed in kernel_launch)
__device__ float g_qp[KSPLIT_][B_ * DM_];   // q projection partials
__device__ float g_kp[KSPLIT_][B_ * DM_];
__device__ float g_vp[KSPLIT_][B_ * DM_];
__device__ float g_op[KSPLIT_][B_ * DM_];   // output projection partials
__device__ float g_attn[B_ * DM_];
__device__ float g_pm[B_ * H_ * SPLIT_];
__device__ float g_pl[B_ * H_ * SPLIT_];
__device__ float g_pa[B_ * H_ * SPLIT_ * DK_];

__device__ __forceinline__ float dot4(float4 a, float4 b) {
    return a.x * b.x + a.y * b.y + a.z * b.z + a.w * b.w;
}
__device__ __forceinline__ float4 add4(float4 a, float4 b) {
    return make_float4(a.x + b.x, a.y + b.y, a.z + b.z, a.w + b.w);
}
__device__ __forceinline__ unsigned smem_u32(const void* p) {
    return (unsigned)__cvta_generic_to_shared(p);
}
__device__ __forceinline__ unsigned long long dup2(float v) {
    unsigned long long r;
    asm("mov.b64 %0, {%1, %1};" : "=l"(r) : "f"(v));
    return r;
}
__device__ __forceinline__ void fma2(unsigned long long& acc,
                                     unsigned long long a,
                                     unsigned long long b) {
    asm("fma.rn.f32x2 %0, %1, %2, %0;" : "+l"(acc) : "l"(a), "l"(b));
}
__device__ __forceinline__ float2 unpk2(unsigned long long p) {
    float2 r;
    asm("mov.b64 {%0, %1}, %2;" : "=f"(r.x), "=f"(r.y) : "l"(p));
    return r;
}

// ---------------------------------------------------------------------------
// Split-K GEMV partial: yp[b][j] = sum_{i in slice} x[b][i] * W[j][i]
// Block: 256 thr = 8 warps x 4 rows = 32 rows; slice = DM/KSPLIT = 1024 cols.
//
// * x pre-packed in smem as batch-pair f32x2 words: xs2[bp][c] = (x[2bp][c],
//   x[2bp+1][c]) -> FFMA2 inner product with only 32 mov.b64 W-dups per chunk.
// * W streamed via PER-THREAD cp.async ring (depth 2): each thread copies
//   exactly the 8 x 16B it will consume, so cp.async.wait_group alone gives
//   visibility -- NO __syncthreads in the main loop.
// Epilogue: butterfly transpose-reduce -> 31 shuffles, 1 STG per lane.
// ---------------------------------------------------------------------------
#define SLICE4_ (DM_ / KSPLIT_ / 4)    // float4 cols per slice (256)
#define CH4_    64                     // float4 cols per chunk
#define NIT_    (SLICE4_ / CH4_)       // chunks per slice (4)
#define NSTG_   2
#define WSTG4_  (8 * 256)              // float4 per W stage (32 KB)
#define XS2N_   (4 * (DM_ / KSPLIT_ / 2))  // float4 entries in xs2 (2048 = 32 KB)

__device__ __forceinline__ void issue_w(const float* __restrict__ W,
                                        int row0, int gcol4,
                                        float4* wstg, int tid, int lane) {
    #pragma unroll
    for (int r = 0; r < 4; r++) {
        #pragma unroll
        for (int h = 0; h < 2; h++) {
            const float4* src = (const float4*)(W + (size_t)(row0 + r) * DM_)
                              + gcol4 + h * 32 + lane;
            const unsigned dst = smem_u32(wstg + (r * 2 + h) * 256 + tid);
            asm volatile("cp.async.cg.shared.global [%0], [%1], 16;"
                         :: "r"(dst), "l"(src));
        }
    }
}

__device__ __forceinline__ void proj_body(const float* __restrict__ x,
                                          const float* __restrict__ W,
                                          float* __restrict__ yp,
                                          int kslice, float4* sm) {
    const int tid  = threadIdx.x;
    const int warp = tid >> 5;
    const int lane = tid & 31;
    const int row0 = blockIdx.x * 32 + warp * 4;
    const int cbase4 = kslice * SLICE4_;     // float4 col base of slice
    const int cbase  = cbase4 * 4;           // scalar col base

    float4* xs2 = sm;                        // [4][512] batch-pair packs
    float4* ws  = sm + XS2N_;                // [NSTG_][WSTG4_]

    // stage x as batch-pair packs: xs2[bp][c2] = (b0[c],b1[c],b0[c+1],b1[c+1])
    #pragma unroll 4
    for (int i = tid; i < XS2N_; i += 256) {
        const int bp = i >> 9;
        const int c2 = i & 511;
        const float2 ea = *(const float2*)(x + (size_t)(2 * bp)     * DM_ + cbase + 2 * c2);
        const float2 eb = *(const float2*)(x + (size_t)(2 * bp + 1) * DM_ + cbase + 2 * c2);
        xs2[i] = make_float4(ea.x, eb.x, ea.y, eb.y);
    }
    // prologue: issue W stage 0 (per-thread; visibility via wait_group)
    issue_w(W, row0, cbase4, ws, tid, lane);
    asm volatile("cp.async.commit_group;");
    __syncthreads();                          // x2 visibility (only block sync)

    unsigned long long acc2[16];              // acc2[r*4+bp]
    #pragma unroll
    for (int i = 0; i < 16; i++) acc2[i] = 0ull;

    #pragma unroll
    for (int it = 0; it < NIT_; ++it) {
        if (it + 1 < NIT_)
            issue_w(W, row0, cbase4 + (it + 1) * CH4_,
                    ws + ((it + 1) & 1) * WSTG4_, tid, lane);
        asm volatile("cp.async.commit_group;");
        asm volatile("cp.async.wait_group 1;");

        const float4* wst = ws + (it & 1) * WSTG4_;
        #pragma unroll
        for (int h = 0; h < 2; h++) {
            const int c4 = it * 64 + h * 32 + lane;   // local float4 col
            // x packs for scalar cols 4c4..4c4+3, all 4 batch-pairs
            ulonglong2 xq[4][2];
            #pragma unroll
            for (int bp = 0; bp < 4; bp++) {
                const ulonglong2* xe =
                    (const ulonglong2*)(xs2 + (size_t)bp * 512 + 2 * c4);
                xq[bp][0] = xe[0];
                xq[bp][1] = xe[1];
            }
            #pragma unroll
            for (int r = 0; r < 4; r++) {
                const float4 w4 = wst[(r * 2 + h) * 256 + tid];
                const unsigned long long wx = dup2(w4.x);
                const unsigned long long wy = dup2(w4.y);
                const unsigned long long wz = dup2(w4.z);
                const unsigned long long ww = dup2(w4.w);
                #pragma unroll
                for (int bp = 0; bp < 4; bp++) {
                    fma2(acc2[r * 4 + bp], wx, xq[bp][0].x);
                    fma2(acc2[r * 4 + bp], wy, xq[bp][0].y);
                    fma2(acc2[r * 4 + bp], wz, xq[bp][1].x);
                    fma2(acc2[r * 4 + bp], ww, xq[bp][1].y);
                }
            }
        }
    }

    // unpack: acc[r*8+b]; acc2[r*4+bp] = (batch 2bp, batch 2bp+1)
    float acc[32];
    #pragma unroll
    for (int r = 0; r < 4; r++)
        #pragma unroll
        for (int bp = 0; bp < 4; bp++) {
            const float2 v = unpk2(acc2[r * 4 + bp]);
            acc[r * 8 + 2 * bp]     = v.x;
            acc[r * 8 + 2 * bp + 1] = v.y;
        }

    // Butterfly transpose-reduce: lane L ends holding full sum of acc[L].
    #pragma unroll
    for (int o = 16; o >= 1; o >>= 1) {
        const bool up = (lane & o) != 0;
        #pragma unroll
        for (int k = 0; k < o; k++) {
            const float keep = up ? acc[k + o] : acc[k];
            const float send = up ? acc[k]     : acc[k + o];
            acc[k] = keep + __shfl_xor_sync(0xffffffffu, send, o);
        }
    }
    const int r = lane >> 3;
    const int b = lane & 7;
    yp[b * DM_ + row0 + r] = acc[0];
}

#define PROJ_SMEM_ ((XS2N_ + NSTG_ * WSTG4_) * (int)sizeof(float4))  // 96 KB

__global__ void __launch_bounds__(256, 2)
proj_qkv_kernel(const float* __restrict__ q_in, const float* __restrict__ k_in,
                const float* __restrict__ v_in,
                const float* __restrict__ Wq, const float* __restrict__ Wk,
                const float* __restrict__ Wv) {
    extern __shared__ float4 sm[];
    const int ks = blockIdx.y;
    const float* x; const float* W; float* y;
    if (blockIdx.z == 0)      { x = q_in; W = Wq; y = g_qp[ks]; }
    else if (blockIdx.z == 1) { x = k_in; W = Wk; y = g_kp[ks]; }
    else                      { x = v_in; W = Wv; y = g_vp[ks]; }
    proj_body(x, W, y, ks, sm);
}

__global__ void __launch_bounds__(256, 2)
proj_out_kernel(const float* __restrict__ Wo) {
    extern __shared__ float4 sm[];
    proj_body(g_attn, Wo, g_op[blockIdx.y], blockIdx.y, sm);
}

__global__ void __launch_bounds__(256)
final_add_kernel(const float* __restrict__ bo, float* __restrict__ out) {
    const int i = blockIdx.x * 256 + threadIdx.x;   // i in [0, B_*DM_)
    out[i] = (g_op[0][i] + g_op[1][i]) + (g_op[2][i] + g_op[3][i])
           + bo[i & (DM_ - 1)];
}

// ---------------------------------------------------------------------------
// Attention, split-K over keys (at HBM roofline — unchanged).
// ---------------------------------------------------------------------------
__global__ void __launch_bounds__(256)
attn_kernel(const float* __restrict__ kc, const float* __restrict__ vc,
            const float* __restrict__ bq, const float* __restrict__ bk,
            const float* __restrict__ bv, const int* __restrict__ cache_len_p) {
    const int bh = blockIdx.x;
    const int b  = bh >> 5;
    const int h  = bh & 31;
    const int s  = blockIdx.y;
    const int L  = cache_len_p[0] + 1;
    const int Lm1 = L - 1;
    const int chunk = (L + SPLIT_ - 1) / SPLIT_;
    const int start = s * chunk;
    const int end   = min(start + chunk, L);

    const int tid  = threadIdx.x;
    const int warp = tid >> 5;
    const int lane = tid & 31;

    const int voff = b * DM_ + h * DK_;
    const float scale = 0.08838834764831843f; // 1/sqrt(128)

    float4 q4   = ((const float4*)(bq + h * DK_))[lane];
    float4 Knew = ((const float4*)(bk + h * DK_))[lane];
    float4 Vnew = ((const float4*)(bv + h * DK_))[lane];
    #pragma unroll
    for (int ks = 0; ks < KSPLIT_; ks++) {
        q4   = add4(q4,   ((const float4*)(g_qp[ks] + voff))[lane]);
        Knew = add4(Knew, ((const float4*)(g_kp[ks] + voff))[lane]);
        Vnew = add4(Vnew, ((const float4*)(g_vp[ks] + voff))[lane]);
    }
    q4.x *= scale; q4.y *= scale; q4.z *= scale; q4.w *= scale;

    const float4* kb = (const float4*)(kc + (((size_t)b * H_ + h) * (size_t)MAXLEN_) * DK_);
    const float4* vb = (const float4*)(vc + (((size_t)b * H_ + h) * (size_t)MAXLEN_) * DK_);

    float m = -CUDART_INF_F;
    float lsum = 0.f;
    float4 a = make_float4(0.f, 0.f, 0.f, 0.f);

    int key = start + warp;
    for (; key + 24 < end; key += 32) {
        const int k1 = key, k2 = key + 8, k3 = key + 16, k4 = key + 24;
        float4 K1 = __ldcs(kb + (size_t)k1 * 32 + lane);
        float4 K2 = __ldcs(kb + (size_t)k2 * 32 + lane);
        float4 K3 = __ldcs(kb + (size_t)k3 * 32 + lane);
        float4 K4 = __ldcs(kb + (size_t)k4 * 32 + lane);
        float4 V1 = __ldcs(vb + (size_t)k1 * 32 + lane);
        float4 V2 = __ldcs(vb + (size_t)k2 * 32 + lane);
        float4 V3 = __ldcs(vb + (size_t)k3 * 32 + lane);
        float4 V4 = __ldcs(vb + (size_t)k4 * 32 + lane);
        if (k1 == Lm1) { K1 = Knew; V1 = Vnew; }
        if (k2 == Lm1) { K2 = Knew; V2 = Vnew; }
        if (k3 == Lm1) { K3 = Knew; V3 = Vnew; }
        if (k4 == Lm1) { K4 = Knew; V4 = Vnew; }

        float s1 = dot4(q4, K1);
        float s2 = dot4(q4, K2);
        float s3 = dot4(q4, K3);
        float s4 = dot4(q4, K4);
        #pragma unroll
        for (int o = 16; o > 0; o >>= 1) {
            s1 += __shfl_xor_sync(0xffffffffu, s1, o);
            s2 += __shfl_xor_sync(0xffffffffu, s2, o);
            s3 += __shfl_xor_sync(0xffffffffu, s3, o);
            s4 += __shfl_xor_sync(0xffffffffu, s4, o);
        }

        const float mn = fmaxf(fmaxf(m, fmaxf(s1, s2)), fmaxf(s3, s4));
        const float corr = __expf(m - mn);
        const float p1 = __expf(s1 - mn);
        const float p2 = __expf(s2 - mn);
        const float p3 = __expf(s3 - mn);
        const float p4 = __expf(s4 - mn);
        lsum = lsum * corr + (p1 + p2) + (p3 + p4);
        a.x = a.x * corr + p1 * V1.x + p2 * V2.x + p3 * V3.x + p4 * V4.x;
        a.y = a.y * corr + p1 * V1.y + p2 * V2.y + p3 * V3.y + p4 * V4.y;
        a.z = a.z * corr + p1 * V1.z + p2 * V2.z + p3 * V3.z + p4 * V4.z;
        a.w = a.w * corr + p1 * V1.w + p2 * V2.w + p3 * V3.w + p4 * V4.w;
        m = mn;
    }
    for (; key < end; key += 8) {
        float4 K1 = __ldcs(kb + (size_t)key * 32 + lane);
        float4 V1 = __ldcs(vb + (size_t)key * 32 + lane);
        if (key == Lm1) { K1 = Knew; V1 = Vnew; }
        float s1 = dot4(q4, K1);
        #pragma unroll
        for (int o = 16; o > 0; o >>= 1) s1 += __shfl_xor_sync(0xffffffffu, s1, o);
        const float mn = fmaxf(m, s1);
        const float corr = __expf(m - mn);
        const float p1 = __expf(s1 - mn);
        lsum = lsum * corr + p1;
        a.x = a.x * corr + p1 * V1.x;
        a.y = a.y * corr + p1 * V1.y;
        a.z = a.z * corr + p1 * V1.z;
        a.w = a.w * corr + p1 * V1.w;
        m = mn;
    }

    // cross-warp combine -> unnormalized block partial
    __shared__ float  sm_m[8];
    __shared__ float  sm_l[8];
    __shared__ float4 sm_a[8][32];
    if (lane == 0) { sm_m[warp] = m; sm_l[warp] = lsum; }
    sm_a[warp][lane] = a;
    __syncthreads();

    if (tid < 128) {
        float M = sm_m[0];
        #pragma unroll
        for (int w = 1; w < 8; w++) M = fmaxf(M, sm_m[w]);
        float Ls = 0.f, o = 0.f;
        const float* sa = (const float*)sm_a;  // [8][128]
        #pragma unroll
        for (int w = 0; w < 8; w++) {
            const float e = __expf(sm_m[w] - M);
            Ls += e * sm_l[w];
            o  += e * sa[w * 128 + tid];
        }
        const int idx = bh * SPLIT_ + s;
        g_pa[idx * DK_ + tid] = o;
        if (tid == 0) { g_pm[idx] = M; g_pl[idx] = Ls; }
    }
}

__global__ void __launch_bounds__(128)
attn_reduce_kernel() {
    const int bh = blockIdx.x;
    const int d  = threadIdx.x;
    float M = -CUDART_INF_F;
    #pragma unroll
    for (int s = 0; s < SPLIT_; s++) M = fmaxf(M, g_pm[bh * SPLIT_ + s]);
    float Ls = 0.f, o = 0.f;
    #pragma unroll
    for (int s = 0; s < SPLIT_; s++) {
        const int idx = bh * SPLIT_ + s;
        const float e = __expf(g_pm[idx] - M);
        Ls += e * g_pl[idx];
        o  += e * g_pa[idx * DK_ + d];
    }
    g_attn[bh * DK_ + d] = o / Ls;
}

// ---------------------------------------------------------------------------
extern "C" void kernel_launch(void* const* d_in, const int* in_sizes, int n_in,
                              void* d_out, int out_size) {
    const float* query = (const float*)d_in[0];
    const float* keyv  = (const float*)d_in[1];
    const float* value = (const float*)d_in[2];
    const float* kc    = (const float*)d_in[3];
    const float* vc    = (const float*)d_in[4];
    const float* Wq    = (const float*)d_in[5];
    const float* bq    = (const float*)d_in[6];
    const float* Wk    = (const float*)d_in[7];
    const float* bk    = (const float*)d_in[8];
    const float* Wv    = (const float*)d_in[9];
    const float* bv    = (const float*)d_in[10];
    const float* Wo    = (const float*)d_in[11];
    const float* bo    = (const float*)d_in[12];
    const int*   clp   = (const int*)d_in[13];

    cudaFuncSetAttribute(proj_qkv_kernel, cudaFuncAttributeMaxDynamicSharedMemorySize, PROJ_SMEM_);
    cudaFuncSetAttribute(proj_out_kernel, cudaFuncAttributeMaxDynamicSharedMemorySize, PROJ_SMEM_);

    dim3 gqkv(DM_ / 32, KSPLIT_, 3);
    proj_qkv_kernel<<<gqkv, 256, PROJ_SMEM_>>>(query, keyv, value, Wq, Wk, Wv);
    dim3 gattn(B_ * H_, SPLIT_);
    attn_kernel<<<gattn, 256>>>(kc, vc, bq, bk, bv, clp);
    attn_reduce_kernel<<<B_ * H_, 128>>>();
    dim3 gout(DM_ / 32, KSPLIT_);
    proj_out_kernel<<<gout, 256, PROJ_SMEM_>>>(Wo);
    final_add_kernel<<<B_ * DM_ / 256, 256>>>(bo, (float*)d_out);
}